// round 6
// baseline (speedup 1.0000x reference)
#include <cuda_runtime.h>
#include <cuda_fp16.h>

// Problem constants
#define DIM   96
#define NBIN  64
#define BSZ   15
#define NFLT  ((size_t)DIM*DIM*DIM*NBIN)   // 56,623,104 halves
#define LINEH (DIM * NBIN)                 // 6144 halves per (z,y) line
#define ZSTRW (DIM*DIM*NBIN/2)             // word (half2) stride per z = 294912
#define YSTRW (DIM*NBIN/2)                 // word stride per y = 3072

// ring geometry (fused YZ kernel): per-y row padded 16 -> 22 halves (11 words)
#define RPADW 11                            // half2 words per y in ring
#define RROWW (DIM * RPADW)                 // 1056 words per ring row
#define RING_BYTES (15 * RROWW * 4)         // 63360 B dynamic smem

// 113 MB fp16 scratch (Xsum) — static device allocation (allowed)
__device__ __align__(16) __half g_h0[NFLT];

__device__ __forceinline__ unsigned pack2(float a, float b) {
    __half2 h = __float22half2_rn(make_float2(a, b));
    return *reinterpret_cast<unsigned*>(&h);
}
__device__ __forceinline__ float2 unpack2(unsigned u) {
    __half2 h = *reinterpret_cast<__half2*>(&u);
    return __half22float2(h);
}

// ---------------------------------------------------------------------------
// Stage 1: gradients -> soft binning (fp16 smem) -> X sliding sum -> fp16
// One block (256 thr) per (z,y) line.
// ---------------------------------------------------------------------------
#define VSTRH 66    // halves per x-row in smem (64 + 2 pad) = 33 words
__global__ void __launch_bounds__(256) binx_kernel(const float* __restrict__ x,
                                                   __half* __restrict__ V)
{
    __shared__ __align__(16) __half Vs[DIM * VSTRH];   // 12.4 KB
    unsigned* Vsu = reinterpret_cast<unsigned*>(Vs);   // 33 words per x-row

    const int tid  = threadIdx.x;
    const int line = blockIdx.x;
    const int yi   = line % DIM;
    const int zi   = line / DIM;

    for (int i = tid; i < DIM * VSTRH / 2; i += 256) Vsu[i] = 0u;
    __syncthreads();

    if (tid < DIM) {
        const int xi = tid;
        const int v  = (zi * DIM + yi) * DIM + xi;

        const float xp = (xi < DIM - 1) ? x[v + 1]       : 0.f;
        const float xm = (xi > 0)       ? x[v - 1]       : 0.f;
        const float yp = (yi < DIM - 1) ? x[v + DIM]     : 0.f;
        const float ym = (yi > 0)       ? x[v - DIM]     : 0.f;
        const float zp = (zi < DIM - 1) ? x[v + DIM*DIM] : 0.f;
        const float zm = (zi > 0)       ? x[v - DIM*DIM] : 0.f;
        const float gx = xp - xm, gy = yp - ym, gz = zp - zm;

        const float EPS    = 2.2204460492503131e-16f;
        const float TWO_PI = (float)(2.0 * 3.14159265358979323846);
        const float PI_F   = (float)(3.14159265358979323846);
        const float TSTEP  = TWO_PI / 8.0f;
        const float PSTEP  = PI_F   / 8.0f;

        const float r   = sqrtf(gx*gx + gy*gy + gz*gz);
        float theta     = atanf(gy / (gx + EPS));
        const float phi = acosf(gz / (r + EPS));
        if (theta < 0.f) theta += TWO_PI;

        const float t_raw = theta / TSTEP;
        const float p_raw = phi   / PSTEP;

        const float ft = floorf(t_raw);
        int lt = (int)ft;            if (lt == 8) lt = 0;
        int lp = (int)floorf(p_raw); if (lp == 8) lp = 0;
        const int ht = (lt + 1) & 7;
        const int hp = (lp + 1) & 7;

        // theta frac intentionally reused for phi ratios (reference bug, faithful)
        const float frac  = t_raw - ft;
        const float w_lo  = fminf(frac, 1.0f - frac);
        const float w_hi  = 1.0f - w_lo;
        const float wp_lo = (frac == 0.0f) ? 1.0f : w_lo;
        const float wp_hi = 1.0f - wp_lo;

        // the 4 target bins are provably distinct -> plain stores
        __half* row = &Vs[xi * VSTRH];
        row[lt*8 + lp] = __float2half_rn(r * w_lo * wp_lo);
        row[ht*8 + lp] = __float2half_rn(r * w_hi * wp_lo);
        row[lt*8 + hp] = __float2half_rn(r * w_lo * wp_hi);
        row[ht*8 + hp] = __float2half_rn(r * w_hi * wp_hi);
    }
    __syncthreads();

    // running X-window: thread = (bin-pair b, segment seg of 12 x)
    {
        const int b   = tid & 31;
        const int seg = tid >> 5;
        const int i0  = seg * 12;

        float w0 = 0.f, w1 = 0.f;
        #pragma unroll
        for (int j = 0; j < BSZ - 1; j++) {
            const int rr = i0 + j;
            if (rr < DIM) {
                const float2 a = unpack2(Vsu[rr * 33 + b]);
                w0 += a.x; w1 += a.y;
            }
        }

        unsigned* outu = reinterpret_cast<unsigned*>(V + (size_t)line * LINEH);
        #pragma unroll
        for (int i = i0; i < i0 + 12; i++) {
            const int hi = i + BSZ - 1;
            if (hi < DIM) {
                const float2 a = unpack2(Vsu[hi * 33 + b]);
                w0 += a.x; w1 += a.y;
            }
            outu[i * 32 + b] = pack2(w0, w1);
            const float2 s = unpack2(Vsu[i * 33 + b]);
            w0 -= s.x; w1 -= s.y;
        }
    }
}

// ---------------------------------------------------------------------------
// Stage 2 (fused Y+Z): block = (x, 16-bin quarter). Per z-row: 96 threads do a
// running Y-window (global reads, trailing hits L1) into a 15-row smem ring;
// all 256 threads run the Z-window in register accumulators and stream fp32 out.
// ---------------------------------------------------------------------------
__global__ void __launch_bounds__(256) yz_kernel(const __half* __restrict__ H,
                                                 float* __restrict__ out)
{
    extern __shared__ __align__(16) unsigned ringu[];   // 15 * RROWW words

    const int tid = threadIdx.x;
    const int xi  = blockIdx.x;      // 0..95
    const int bq  = blockIdx.y;      // 0..3 (16 bins)

    // ---- B (Y-window) thread mapping: threads 0..95 ----
    const int colB = tid & 7;        // half2 column within 16-bin chunk
    const int segB = tid >> 3;       // 0..11 (for tid<96), 8 y each
    const int y0   = segB * 8;
    const unsigned* Hu = reinterpret_cast<const unsigned*>(H);
    const int xw = xi * 32 + bq * 8 + colB;   // word offset within a (z,y) entry

    // ---- C (Z-window) unit mapping: u = tid + k*256 -> (y = u>>3, col = u&7) ----
    float2 acc[3];
    #pragma unroll
    for (int k = 0; k < 3; k++) acc[k] = make_float2(0.f, 0.f);

    const int cy[3]  = { (tid      ) >> 3, (tid + 256) >> 3, (tid + 512) >> 3 };
    const int cc[3]  = { tid & 7, tid & 7, tid & 7 };
    // out float2 base offset for (y, col) of each unit (z' added per row)
    size_t obase[3];
    int    rbase[3];
    #pragma unroll
    for (int k = 0; k < 3; k++) {
        obase[k] = (size_t)cy[k] * (DIM * NBIN) + (size_t)xi * NBIN + bq * 16 + cc[k] * 2;
        rbase[k] = cy[k] * RPADW + cc[k];
    }

    for (int z = 0; z < DIM; z++) {
        // ---- B: Ysum of row z -> ring[z%15] ----
        if (tid < 96) {
            const unsigned* p = Hu + (size_t)z * ZSTRW + xw;
            float w0 = 0.f, w1 = 0.f;
            #pragma unroll
            for (int j = 0; j < BSZ - 1; j++) {
                const int yy = y0 + j;
                if (yy < DIM) {
                    const float2 a = unpack2(p[yy * YSTRW]);
                    w0 += a.x; w1 += a.y;
                }
            }
            unsigned* rrow = ringu + (z % 15) * RROWW;
            #pragma unroll
            for (int i = y0; i < y0 + 8; i++) {
                const int hi = i + BSZ - 1;
                if (hi < DIM) {
                    const float2 a = unpack2(p[hi * YSTRW]);
                    w0 += a.x; w1 += a.y;
                }
                rrow[i * RPADW + colB] = pack2(w0, w1);
                const float2 s = unpack2(p[i * YSTRW]);
                w0 -= s.x; w1 -= s.y;
            }
        }
        __syncthreads();

        // ---- C: Z running window ----
        {
            const unsigned* rnew = ringu + (z % 15) * RROWW;
            #pragma unroll
            for (int k = 0; k < 3; k++) {
                const float2 a = unpack2(rnew[rbase[k]]);
                acc[k].x += a.x; acc[k].y += a.y;
            }
            if (z >= BSZ - 1) {
                const int zp = z - (BSZ - 1);
                const unsigned* rold = ringu + (zp % 15) * RROWW;
                float* orow = out + (size_t)zp * (DIM * DIM * NBIN);
                #pragma unroll
                for (int k = 0; k < 3; k++) {
                    __stcs(reinterpret_cast<float2*>(orow + obase[k]), acc[k]);
                    const float2 s = unpack2(rold[rbase[k]]);
                    acc[k].x -= s.x; acc[k].y -= s.y;
                }
            }
        }
        __syncthreads();
    }

    // ---- tail: z' = 82..95 (window clamps past the end) ----
    for (int zp = DIM - BSZ + 1; zp < DIM; zp++) {
        const unsigned* rold = ringu + (zp % 15) * RROWW;
        float* orow = out + (size_t)zp * (DIM * DIM * NBIN);
        #pragma unroll
        for (int k = 0; k < 3; k++) {
            __stcs(reinterpret_cast<float2*>(orow + obase[k]), acc[k]);
            const float2 s = unpack2(rold[rbase[k]]);
            acc[k].x -= s.x; acc[k].y -= s.y;
        }
    }
}

// ---------------------------------------------------------------------------
extern "C" void kernel_launch(void* const* d_in, const int* in_sizes, int n_in,
                              void* d_out, int out_size)
{
    const float* x = (const float*)d_in[0];

    void* p0 = nullptr;
    cudaGetSymbolAddress(&p0, g_h0);

    cudaFuncSetAttribute(yz_kernel, cudaFuncAttributeMaxDynamicSharedMemorySize,
                         RING_BYTES);

    binx_kernel<<<DIM * DIM, 256>>>(x, (__half*)p0);         // x -> Xsum (fp16)

    dim3 g(DIM, 4);                                           // (x, bin-quarter)
    yz_kernel<<<g, 256, RING_BYTES>>>((const __half*)p0, (float*)d_out);
}